// round 1
// baseline (speedup 1.0000x reference)
#include <cuda_runtime.h>
#include <math.h>

// Problem constants (fixed shapes per reference)
#define N_TOK 4096
#define DIM   2048
#define ODIM  2048
#define NE    8

// GEMM tiling
#define BM 128
#define BN 128
#define BK 16

// ---------------------------------------------------------------------------
// Device-global scratch (allocation-free workaround per harness rules)
// ---------------------------------------------------------------------------
__device__ int   g_count[NE];            // tokens routed to each expert
__device__ int   g_tok[NE][N_TOK];       // token index lists per expert
__device__ float g_w  [NE][N_TOK];       // routing weight per (expert, slot)

// ---------------------------------------------------------------------------
// Kernel 0: zero output + reset expert counters
// ---------------------------------------------------------------------------
__global__ void zero_kernel(float4* __restrict__ out, int n4) {
    int i = blockIdx.x * blockDim.x + threadIdx.x;
    if (i < n4) out[i] = make_float4(0.f, 0.f, 0.f, 0.f);
    if (blockIdx.x == 0 && threadIdx.x < NE) g_count[threadIdx.x] = 0;
}

// ---------------------------------------------------------------------------
// Kernel 1: gating = x @ Wg + bg ; top-2 ; softmax over the two logits ;
//           append (token, weight) to each selected expert's list.
// One warp per token.
// ---------------------------------------------------------------------------
__global__ void gating_kernel(const float* __restrict__ x,
                              const float* __restrict__ Wg,
                              const float* __restrict__ bg) {
    int warp = (blockIdx.x * blockDim.x + threadIdx.x) >> 5;
    int lane = threadIdx.x & 31;
    if (warp >= N_TOK) return;

    const float* xr = x + (size_t)warp * DIM;
    float acc[NE];
#pragma unroll
    for (int e = 0; e < NE; e++) acc[e] = 0.f;

    for (int k = lane; k < DIM; k += 32) {
        float xv = xr[k];
        const float* wr = Wg + (size_t)k * NE;
#pragma unroll
        for (int e = 0; e < NE; e++) acc[e] = fmaf(xv, wr[e], acc[e]);
    }
#pragma unroll
    for (int e = 0; e < NE; e++) {
#pragma unroll
        for (int off = 16; off > 0; off >>= 1)
            acc[e] += __shfl_xor_sync(0xFFFFFFFFu, acc[e], off);
    }

    if (lane == 0) {
        float v[NE];
#pragma unroll
        for (int e = 0; e < NE; e++) v[e] = acc[e] + bg[e];

        // top-1 (lowest index wins ties, matching lax.top_k)
        int i0 = 0;
#pragma unroll
        for (int e = 1; e < NE; e++) if (v[e] > v[i0]) i0 = e;
        // top-2
        int i1 = (i0 == 0) ? 1 : 0;
#pragma unroll
        for (int e = 0; e < NE; e++) {
            if (e != i0 && v[e] > v[i1]) i1 = e;
        }

        // softmax over [v[i0], v[i1]] with v[i0] >= v[i1]
        float t  = expf(v[i1] - v[i0]);
        float w0 = 1.0f / (1.0f + t);
        float w1 = 1.0f - w0;

        int p0 = atomicAdd(&g_count[i0], 1);
        g_tok[i0][p0] = warp;  g_w[i0][p0] = w0;
        int p1 = atomicAdd(&g_count[i1], 1);
        g_tok[i1][p1] = warp;  g_w[i1][p1] = w1;
    }
}

// ---------------------------------------------------------------------------
// Kernel 2: per-expert gather-GEMM.
//   For expert e, tokens ts[m0..m0+127]:
//     C[m, n] = sum_k x[ts[m], k] * We[e, k, n0+n]
//     out[ts[m], n0+n] += w[m] * (C[m,n] + be[e, n0+n])
// 256 threads, BM=BN=128, BK=16, 8x8 per thread, double-buffered smem.
// Grid: (ODIM/BN, N_TOK/BM, NE). Tiles beyond g_count[e] exit immediately.
// ---------------------------------------------------------------------------
__global__ __launch_bounds__(256, 2)
void moe_gemm_kernel(const float* __restrict__ x,
                     const float* __restrict__ We,
                     const float* __restrict__ be,
                     float* __restrict__ out) {
    const int e     = blockIdx.z;
    const int count = g_count[e];
    const int m0    = blockIdx.y * BM;
    if (m0 >= count) return;
    const int n0    = blockIdx.x * BN;

    __shared__ float As[2][BK][BM];
    __shared__ float Bs[2][BK][BN];
    __shared__ int   ts[BM];
    __shared__ float ws[BM];

    const int tid = threadIdx.x;

    if (tid < BM) {
        int mi = m0 + tid;
        if (mi < count) { ts[tid] = g_tok[e][mi]; ws[tid] = g_w[e][mi]; }
        else            { ts[tid] = 0;            ws[tid] = 0.f;       }
    }
    __syncthreads();

    // ---- load mappings ----
    // A: each thread owns one gathered row (m = tid&127) and fetches the
    //    float4 chunks kq and kq+2 of the 16-wide K slice (kq = tid>>7).
    const int am  = tid & 127;
    const int akq = tid >> 7;            // 0..1
    const float* arow = x + (size_t)ts[am] * DIM;

    // B: thread loads rows bk and bk+8 of the K slice, float4 column bn4.
    const int bn4 = tid & 31;
    const int bk  = tid >> 5;            // 0..7
    const float* Wbase = We + ((size_t)e * DIM) * ODIM + n0;

    // thread tile coordinates
    const int tx = tid & 15;             // n / 8
    const int ty = tid >> 4;             // m / 8

    float acc[8][8];
#pragma unroll
    for (int i = 0; i < 8; i++)
#pragma unroll
        for (int j = 0; j < 8; j++) acc[i][j] = 0.f;

    float4 aF0, aF1, bF0, bF1;

    // ---- prologue: fetch stage 0 ----
    {
        const int k0 = 0;
        aF0 = *(const float4*)(arow + k0 + akq * 4);
        aF1 = *(const float4*)(arow + k0 + (akq + 2) * 4);
        bF0 = *(const float4*)(Wbase + (size_t)(k0 + bk)     * ODIM + bn4 * 4);
        bF1 = *(const float4*)(Wbase + (size_t)(k0 + bk + 8) * ODIM + bn4 * 4);

        As[0][akq * 4 + 0][am] = aF0.x;
        As[0][akq * 4 + 1][am] = aF0.y;
        As[0][akq * 4 + 2][am] = aF0.z;
        As[0][akq * 4 + 3][am] = aF0.w;
        As[0][akq * 4 + 8][am] = aF1.x;
        As[0][akq * 4 + 9][am] = aF1.y;
        As[0][akq * 4 +10][am] = aF1.z;
        As[0][akq * 4 +11][am] = aF1.w;
        *(float4*)&Bs[0][bk]    [bn4 * 4] = bF0;
        *(float4*)&Bs[0][bk + 8][bn4 * 4] = bF1;
    }
    __syncthreads();

    int buf = 0;
    const int KT = DIM / BK;             // 128
    for (int kt = 0; kt < KT; ++kt) {
        // prefetch next stage into registers
        if (kt + 1 < KT) {
            const int k0 = (kt + 1) * BK;
            aF0 = *(const float4*)(arow + k0 + akq * 4);
            aF1 = *(const float4*)(arow + k0 + (akq + 2) * 4);
            bF0 = *(const float4*)(Wbase + (size_t)(k0 + bk)     * ODIM + bn4 * 4);
            bF1 = *(const float4*)(Wbase + (size_t)(k0 + bk + 8) * ODIM + bn4 * 4);
        }

        // compute current stage
#pragma unroll
        for (int kk = 0; kk < BK; ++kk) {
            float a[8], b[8];
            *(float4*)&a[0] = *(const float4*)&As[buf][kk][ty * 8];
            *(float4*)&a[4] = *(const float4*)&As[buf][kk][ty * 8 + 4];
            *(float4*)&b[0] = *(const float4*)&Bs[buf][kk][tx * 8];
            *(float4*)&b[4] = *(const float4*)&Bs[buf][kk][tx * 8 + 4];
#pragma unroll
            for (int i = 0; i < 8; i++)
#pragma unroll
                for (int j = 0; j < 8; j++)
                    acc[i][j] = fmaf(a[i], b[j], acc[i][j]);
        }

        // commit prefetched stage to the other buffer
        if (kt + 1 < KT) {
            int nb = buf ^ 1;
            As[nb][akq * 4 + 0][am] = aF0.x;
            As[nb][akq * 4 + 1][am] = aF0.y;
            As[nb][akq * 4 + 2][am] = aF0.z;
            As[nb][akq * 4 + 3][am] = aF0.w;
            As[nb][akq * 4 + 8][am] = aF1.x;
            As[nb][akq * 4 + 9][am] = aF1.y;
            As[nb][akq * 4 +10][am] = aF1.z;
            As[nb][akq * 4 +11][am] = aF1.w;
            *(float4*)&Bs[nb][bk]    [bn4 * 4] = bF0;
            *(float4*)&Bs[nb][bk + 8][bn4 * 4] = bF1;
            __syncthreads();
            buf = nb;
        }
    }

    // ---- epilogue: out[t, n] += w * (acc + be[e, n]) ----
    const float* berow = be + (size_t)e * ODIM + n0 + tx * 8;
#pragma unroll
    for (int i = 0; i < 8; i++) {
        int m = ty * 8 + i;
        if (m0 + m < count) {
            int   t  = ts[m];
            float wv = ws[m];
            float* orow = out + (size_t)t * ODIM + n0 + tx * 8;
#pragma unroll
            for (int j = 0; j < 8; j++) {
                atomicAdd(&orow[j], wv * (acc[i][j] + berow[j]));
            }
        }
    }
}

// ---------------------------------------------------------------------------
// Launch
// inputs: x[N,D] f32, Wg[D,E] f32, bg[E] f32, We[E,D,O] f32, be[E,O] f32
// output: out[N,O] f32
// ---------------------------------------------------------------------------
extern "C" void kernel_launch(void* const* d_in, const int* in_sizes, int n_in,
                              void* d_out, int out_size) {
    const float* x  = (const float*)d_in[0];
    const float* Wg = (const float*)d_in[1];
    const float* bg = (const float*)d_in[2];
    const float* We = (const float*)d_in[3];
    const float* be = (const float*)d_in[4];
    float* out = (float*)d_out;

    // 1) zero output + reset counters
    int n4 = out_size / 4;
    zero_kernel<<<(n4 + 255) / 256, 256>>>((float4*)out, n4);

    // 2) gating + routing (one warp per token)
    gating_kernel<<<(N_TOK * 32) / 256, 256>>>(x, Wg, bg);

    // 3) per-expert gather-GEMM (worst-case grid; empty tiles exit)
    dim3 grid(ODIM / BN, N_TOK / BM, NE);
    moe_gemm_kernel<<<grid, 256>>>(x, We, be, out);
}

// round 3
// speedup vs baseline: 2.7286x; 2.7286x over previous
#include <cuda_runtime.h>
#include <math.h>
#include <stdint.h>

// ---------------------------------------------------------------------------
// Problem constants
// ---------------------------------------------------------------------------
#define N_TOK 4096
#define DIM   2048
#define ODIM  2048
#define NE    8

// GEMM tiling
#define BM 128
#define BN 128
#define BK 32
#define STAGES 4
#define KT_TOTAL (DIM / BK)            // 64

// SMEM strides chosen for conflict-free fragment LDS (see analysis)
#define A_STRIDE 36                    // floats per A row  (banks: 4g + t4)
#define B_STRIDE 136                   // floats per B row  (banks: 8t4 + g)
#define A_STG (BM * A_STRIDE * 4)      // 18432 B
#define B_STG (BK * B_STRIDE * 4)      // 17408 B

#define OFF_TS   0
#define OFF_WS   512
#define OFF_A    1024
#define OFF_B    (OFF_A + STAGES * A_STG)            // 74752
#define SMEM_TOTAL (OFF_B + STAGES * B_STG)          // 144384

// ---------------------------------------------------------------------------
// Device scratch (allocation-free)
// ---------------------------------------------------------------------------
__device__ float g_partial[(size_t)N_TOK * 2 * ODIM];   // per-(token,rank) partials
__device__ int   g_count[NE];
__device__ int   g_slot[NE][N_TOK];                     // token*2 + rank
__device__ float g_w[NE][N_TOK];

// ---------------------------------------------------------------------------
// PTX helpers (base sm_100 target — NO tcgen05 / no 'a' features)
// ---------------------------------------------------------------------------
__device__ __forceinline__ uint32_t smem_u32(const void* p) {
    uint32_t a;
    asm("{ .reg .u64 t; cvta.to.shared.u64 t, %1; cvt.u32.u64 %0, t; }" : "=r"(a) : "l"(p));
    return a;
}
__device__ __forceinline__ uint32_t tf32_rna(float v) {
    uint32_t u;
    asm("cvt.rna.tf32.f32 %0, %1;" : "=r"(u) : "f"(v));
    return u;
}
__device__ __forceinline__ void cp_async16(uint32_t smem_addr, const void* gmem) {
    asm volatile("cp.async.cg.shared.global [%0], [%1], 16;" :: "r"(smem_addr), "l"(gmem));
}
__device__ __forceinline__ void cp_commit() {
    asm volatile("cp.async.commit_group;");
}
template <int N>
__device__ __forceinline__ void cp_wait() {
    asm volatile("cp.async.wait_group %0;" :: "n"(N));
}
__device__ __forceinline__ void mma_tf32(float c[4], const uint32_t a[4], const uint32_t b[2]) {
    asm volatile(
        "mma.sync.aligned.m16n8k8.row.col.f32.tf32.tf32.f32 "
        "{%0,%1,%2,%3}, {%4,%5,%6,%7}, {%8,%9}, {%0,%1,%2,%3};"
        : "+f"(c[0]), "+f"(c[1]), "+f"(c[2]), "+f"(c[3])
        : "r"(a[0]), "r"(a[1]), "r"(a[2]), "r"(a[3]), "r"(b[0]), "r"(b[1]));
}

// ---------------------------------------------------------------------------
// Kernel 0: reset expert counters
// ---------------------------------------------------------------------------
__global__ void reset_kernel() {
    if (threadIdx.x < NE) g_count[threadIdx.x] = 0;
}

// ---------------------------------------------------------------------------
// Kernel 1: gating + top-2 routing (one warp per token)
// ---------------------------------------------------------------------------
__global__ void gating_kernel(const float* __restrict__ x,
                              const float* __restrict__ Wg,
                              const float* __restrict__ bg) {
    int warp = (blockIdx.x * blockDim.x + threadIdx.x) >> 5;
    int lane = threadIdx.x & 31;
    if (warp >= N_TOK) return;

    const float* xr = x + (size_t)warp * DIM;
    float acc[NE];
#pragma unroll
    for (int e = 0; e < NE; e++) acc[e] = 0.f;
    for (int k = lane; k < DIM; k += 32) {
        float xv = xr[k];
        const float* wr = Wg + (size_t)k * NE;
#pragma unroll
        for (int e = 0; e < NE; e++) acc[e] = fmaf(xv, wr[e], acc[e]);
    }
#pragma unroll
    for (int e = 0; e < NE; e++) {
#pragma unroll
        for (int off = 16; off > 0; off >>= 1)
            acc[e] += __shfl_xor_sync(0xFFFFFFFFu, acc[e], off);
    }
    if (lane == 0) {
        float v[NE];
#pragma unroll
        for (int e = 0; e < NE; e++) v[e] = acc[e] + bg[e];
        int i0 = 0;
#pragma unroll
        for (int e = 1; e < NE; e++) if (v[e] > v[i0]) i0 = e;
        int i1 = (i0 == 0) ? 1 : 0;
#pragma unroll
        for (int e = 0; e < NE; e++) if (e != i0 && v[e] > v[i1]) i1 = e;

        float t  = expf(v[i1] - v[i0]);
        float w0 = 1.0f / (1.0f + t);
        float w1 = 1.0f - w0;

        int p0 = atomicAdd(&g_count[i0], 1);
        g_slot[i0][p0] = warp * 2 + 0;  g_w[i0][p0] = w0;
        int p1 = atomicAdd(&g_count[i1], 1);
        g_slot[i1][p1] = warp * 2 + 1;  g_w[i1][p1] = w1;
    }
}

// ---------------------------------------------------------------------------
// Kernel 2: tf32 mma.sync gather-GEMM.
//   D[m,n] = sum_k x[tok(m),k] * We[e, k, n0+n]      (B is native k-major!)
//   partial[slot(m), n0+n] = w(m) * (D[m,n] + be[e, n0+n])
// 256 threads = 8 warps (4 along M x 2 along N), warp tile 32x64.
// 4-stage cp.async pipeline; rna tf32 rounding applied at fragment load.
// ---------------------------------------------------------------------------
__global__ void __launch_bounds__(256, 1)
moe_mma_kernel(const float* __restrict__ x,
               const float* __restrict__ We,
               const float* __restrict__ be) {
    const int e     = blockIdx.z;
    const int count = g_count[e];
    const int m0    = blockIdx.y * BM;
    if (m0 >= count) return;
    const int n0    = blockIdx.x * BN;

    extern __shared__ char smem[];
    const uint32_t sb = smem_u32(smem);
    const int tid  = threadIdx.x;
    const int wid  = tid >> 5;
    const int lane = tid & 31;

    int*   ts_s = (int*)(smem + OFF_TS);
    float* ws_s = (float*)(smem + OFF_WS);
    if (tid < BM) {
        int mi = m0 + tid;
        if (mi < count) { ts_s[tid] = g_slot[e][mi]; ws_s[tid] = g_w[e][mi]; }
        else            { ts_s[tid] = 0;             ws_s[tid] = 0.f;        }
    }
    __syncthreads();

    // ---- per-thread cp.async source/dst precompute ----
    // A: 1024 16B chunks/stage. chunk c = tid + 256j: row = c>>3, col4 = c&7.
    const float* aptr[4]; uint32_t asm_off[4];
#pragma unroll
    for (int j = 0; j < 4; j++) {
        int c = tid + 256 * j;
        int row = c >> 3, col4 = c & 7;
        aptr[j]   = x + (size_t)(ts_s[row] >> 1) * DIM + col4 * 4;
        asm_off[j] = sb + OFF_A + (uint32_t)(row * (A_STRIDE * 4) + col4 * 16);
    }
    // B: 1024 16B chunks/stage. chunk c: row = c>>5 (k), col4 = c&31 (n/4).
    const float* bptr[4]; uint32_t bsm_off[4];
#pragma unroll
    for (int j = 0; j < 4; j++) {
        int c = tid + 256 * j;
        int row = c >> 5, col4 = c & 31;
        bptr[j]   = We + ((size_t)e * DIM + row) * ODIM + n0 + col4 * 4;
        bsm_off[j] = sb + OFF_B + (uint32_t)(row * (B_STRIDE * 4) + col4 * 16);
    }

    // ---- prologue: fill stages 0..2 ----
#pragma unroll
    for (int kt = 0; kt < STAGES - 1; kt++) {
#pragma unroll
        for (int j = 0; j < 4; j++)
            cp_async16(asm_off[j] + kt * A_STG, aptr[j] + kt * BK);
#pragma unroll
        for (int j = 0; j < 4; j++)
            cp_async16(bsm_off[j] + kt * B_STG, bptr[j] + (size_t)kt * BK * ODIM);
        cp_commit();
    }

    const int wm = wid & 3;            // warp row block (32 rows)
    const int wn = wid >> 2;           // warp col block (64 cols)
    const int g  = lane >> 2;          // group id (0..7)
    const int t4 = lane & 3;           // thread in group

    float acc[2][8][4];
#pragma unroll
    for (int mi = 0; mi < 2; mi++)
#pragma unroll
        for (int ni = 0; ni < 8; ni++)
#pragma unroll
            for (int r = 0; r < 4; r++) acc[mi][ni][r] = 0.f;

    // fragment base offsets (bytes, within a stage)
    const uint32_t a_base = (uint32_t)((wm * 32 + g) * (A_STRIDE * 4) + t4 * 4);
    const uint32_t b_base = (uint32_t)(t4 * (B_STRIDE * 4) + (wn * 64 + g) * 4);

    // ---- main loop ----
    for (int kt = 0; kt < KT_TOTAL; ++kt) {
        cp_wait<STAGES - 2>();
        __syncthreads();

        // issue stage kt+3 (overwrites slot read in iteration kt-1)
        if (kt + STAGES - 1 < KT_TOTAL) {
            const int kn = kt + STAGES - 1;
            const int s  = kn & (STAGES - 1);
#pragma unroll
            for (int j = 0; j < 4; j++)
                cp_async16(asm_off[j] + s * A_STG, aptr[j] + kn * BK);
#pragma unroll
            for (int j = 0; j < 4; j++)
                cp_async16(bsm_off[j] + s * B_STG, bptr[j] + (size_t)kn * BK * ODIM);
            cp_commit();
        } else {
            cp_commit();               // keep group count in step
        }

        // compute stage kt
        const char* As = smem + OFF_A + (kt & (STAGES - 1)) * A_STG;
        const char* Bs = smem + OFF_B + (kt & (STAGES - 1)) * B_STG;
#pragma unroll
        for (int kk = 0; kk < 4; kk++) {
            uint32_t a[2][4];
#pragma unroll
            for (int mi = 0; mi < 2; mi++) {
                const float* p = (const float*)(As + a_base + mi * (16 * A_STRIDE * 4) + kk * 32);
                a[mi][0] = tf32_rna(p[0]);
                a[mi][1] = tf32_rna(p[8 * A_STRIDE]);
                a[mi][2] = tf32_rna(p[4]);
                a[mi][3] = tf32_rna(p[8 * A_STRIDE + 4]);
            }
            uint32_t b[8][2];
#pragma unroll
            for (int ni = 0; ni < 8; ni++) {
                const float* q = (const float*)(Bs + b_base + kk * (8 * B_STRIDE * 4) + ni * 32);
                b[ni][0] = tf32_rna(q[0]);
                b[ni][1] = tf32_rna(q[4 * B_STRIDE]);
            }
#pragma unroll
            for (int mi = 0; mi < 2; mi++)
#pragma unroll
                for (int ni = 0; ni < 8; ni++)
                    mma_tf32(acc[mi][ni], a[mi], b[ni]);
        }
    }

    // ---- epilogue: partial[slot, n] = w * (D + be) ----
    const float* bee = be + (size_t)e * ODIM + n0;
#pragma unroll
    for (int mi = 0; mi < 2; mi++) {
        const int ml0 = wm * 32 + mi * 16 + g;       // row for c0,c1
        const int ml1 = ml0 + 8;                     // row for c2,c3
        const bool v0 = (m0 + ml0) < count;
        const bool v1 = (m0 + ml1) < count;
        const int   s0 = ts_s[ml0], s1 = ts_s[ml1];
        const float w0 = ws_s[ml0], w1 = ws_s[ml1];
        float* d0 = g_partial + (size_t)s0 * ODIM + n0;
        float* d1 = g_partial + (size_t)s1 * ODIM + n0;
#pragma unroll
        for (int ni = 0; ni < 8; ni++) {
            const int nc = wn * 64 + ni * 8 + t4 * 2;
            const float be0 = bee[nc], be1 = bee[nc + 1];
            if (v0) {
                float2 o;
                o.x = w0 * (acc[mi][ni][0] + be0);
                o.y = w0 * (acc[mi][ni][1] + be1);
                *(float2*)(d0 + nc) = o;
            }
            if (v1) {
                float2 o;
                o.x = w1 * (acc[mi][ni][2] + be0);
                o.y = w1 * (acc[mi][ni][3] + be1);
                *(float2*)(d1 + nc) = o;
            }
        }
    }
}

// ---------------------------------------------------------------------------
// Kernel 3: out[t, n] = partial[2t, n] + partial[2t+1, n]
// ---------------------------------------------------------------------------
__global__ void combine_kernel(float4* __restrict__ out) {
    int i  = blockIdx.x * blockDim.x + threadIdx.x;   // float4 index, exactly N*O/4
    int t  = i >> 9;                                  // ODIM/4 = 512
    int n4 = i & 511;
    const float4* p0 = (const float4*)(g_partial + (size_t)(t * 2)     * ODIM) + n4;
    const float4* p1 = (const float4*)(g_partial + (size_t)(t * 2 + 1) * ODIM) + n4;
    float4 a = *p0, b = *p1;
    out[i] = make_float4(a.x + b.x, a.y + b.y, a.z + b.z, a.w + b.w);
}

// ---------------------------------------------------------------------------
// Launch
// ---------------------------------------------------------------------------
extern "C" void kernel_launch(void* const* d_in, const int* in_sizes, int n_in,
                              void* d_out, int out_size) {
    const float* x  = (const float*)d_in[0];
    const float* Wg = (const float*)d_in[1];
    const float* bg = (const float*)d_in[2];
    const float* We = (const float*)d_in[3];
    const float* be = (const float*)d_in[4];
    float* out = (float*)d_out;

    static int smem_set = 0;
    if (!smem_set) {
        cudaFuncSetAttribute(moe_mma_kernel, cudaFuncAttributeMaxDynamicSharedMemorySize, SMEM_TOTAL);
        smem_set = 1;
    }

    // 1) reset routing counters
    reset_kernel<<<1, 32>>>();

    // 2) gating + top-2 routing
    gating_kernel<<<(N_TOK * 32) / 256, 256>>>(x, Wg, bg);

    // 3) tf32 mma.sync gather-GEMM into partial (worst-case grid; empty tiles exit)
    dim3 ggrid(ODIM / BN, N_TOK / BM, NE);
    moe_mma_kernel<<<ggrid, 256, SMEM_TOTAL>>>(x, We, be);

    // 4) combine the two expert contributions per token
    combine_kernel<<<(N_TOK * ODIM / 4) / 256, 256>>>((float4*)out);
}